// round 1
// baseline (speedup 1.0000x reference)
#include <cuda_runtime.h>
#include <cstdint>

// Problem constants (fixed shapes)
#define BL_   2048           // B*L = 2*1024
#define L_    1024
#define D_    1024
#define ED_   2048
#define N_    16
#define R_    32
#define NPROJ 4096           // 2*ED

// ---------------- device scratch (static, no allocation) ----------------
__device__ float g_xs  [BL_ * ED_];   // raw xs half of in_proj output
__device__ float g_z   [BL_ * ED_];   // raw z  half of in_proj output
__device__ float g_xsc [BL_ * ED_];   // conv + silu applied
__device__ float g_xdbl[BL_ * 64];    // x_proj output (R + 2N = 64)
__device__ float g_delta[BL_ * ED_];  // softplus(dt_proj)
__device__ float g_y   [BL_ * ED_];   // y * silu(z)
__device__ float g_A   [ED_ * N_];    // -exp(A_log)

// ---------------- tiny precompute: A = -exp(A_log) ----------------
__global__ void prep_A_kernel(const float* __restrict__ A_log) {
    int i = blockIdx.x * blockDim.x + threadIdx.x;
    if (i < ED_ * N_) g_A[i] = -expf(A_log[i]);
}

// ---------------- generic NT GEMM: C[m][n] = sum_k A[m][k]*B[n][k] ----------------
// EPI 0: plain store to C (ldc = N)
// EPI 1: split store: n <  N/2 -> g_xs[m*(N/2)+n]
//                     n >= N/2 -> g_z [m*(N/2)+n-N/2]
template<int BM, int BN, int BK, int TM, int TN, int EPI>
__global__ void __launch_bounds__((BM/TM)*(BN/TN))
gemm_nt(const float* __restrict__ A, const float* __restrict__ B,
        float* __restrict__ C, int M, int N, int K)
{
    constexpr int THREADS = (BM/TM)*(BN/TN);
    __shared__ float As[BK * BM];
    __shared__ float Bs[BK * BN];

    const int t  = threadIdx.x;
    const int m0 = blockIdx.y * BM;
    const int n0 = blockIdx.x * BN;
    const int tr = t / (BN/TN);
    const int tc = t % (BN/TN);

    float acc[TM][TN];
#pragma unroll
    for (int i = 0; i < TM; i++)
#pragma unroll
        for (int j = 0; j < TN; j++) acc[i][j] = 0.f;

    constexpr int AF4 = BM * BK / 4;
    constexpr int BF4 = BN * BK / 4;
    constexpr int ALD = AF4 / THREADS;   // float4 loads per thread (>=1 for our configs)
    constexpr int BLD = BF4 / THREADS;

    for (int k0 = 0; k0 < K; k0 += BK) {
#pragma unroll
        for (int j = 0; j < ALD; j++) {
            int i   = t + j * THREADS;
            int row = i / (BK/4);
            int c4  = i % (BK/4);
            float4 v = *(const float4*)(A + (size_t)(m0 + row) * K + k0 + c4*4);
            As[(c4*4+0)*BM + row] = v.x;
            As[(c4*4+1)*BM + row] = v.y;
            As[(c4*4+2)*BM + row] = v.z;
            As[(c4*4+3)*BM + row] = v.w;
        }
#pragma unroll
        for (int j = 0; j < BLD; j++) {
            int i   = t + j * THREADS;
            int row = i / (BK/4);
            int c4  = i % (BK/4);
            float4 v = *(const float4*)(B + (size_t)(n0 + row) * K + k0 + c4*4);
            Bs[(c4*4+0)*BN + row] = v.x;
            Bs[(c4*4+1)*BN + row] = v.y;
            Bs[(c4*4+2)*BN + row] = v.z;
            Bs[(c4*4+3)*BN + row] = v.w;
        }
        __syncthreads();

#pragma unroll
        for (int kk = 0; kk < BK; kk++) {
            float af[TM], bf[TN];
#pragma unroll
            for (int i = 0; i < TM; i++) af[i] = As[kk*BM + tr*TM + i];
#pragma unroll
            for (int j = 0; j < TN; j++) bf[j] = Bs[kk*BN + tc*TN + j];
#pragma unroll
            for (int i = 0; i < TM; i++)
#pragma unroll
                for (int j = 0; j < TN; j++)
                    acc[i][j] = fmaf(af[i], bf[j], acc[i][j]);
        }
        __syncthreads();
    }

    // epilogue
#pragma unroll
    for (int i = 0; i < TM; i++) {
        int m = m0 + tr*TM + i;
#pragma unroll
        for (int j = 0; j < TN; j++) {
            int n = n0 + tc*TN + j;
            if (EPI == 0) {
                C[(size_t)m * N + n] = acc[i][j];
            } else {
                int half = N >> 1;
                if (n < half) g_xs[(size_t)m * half + n] = acc[i][j];
                else          g_z [(size_t)m * half + (n - half)] = acc[i][j];
            }
        }
    }
}

// ---------------- depthwise conv1d (k=3, pad 1) + silu ----------------
// xs layout (m, e) with m = b*L + l ; conv along l within batch
__global__ void conv_silu_kernel(const float* __restrict__ w,
                                 const float* __restrict__ b)
{
    int idx = blockIdx.x * blockDim.x + threadIdx.x;   // over BL_ * (ED_/4)
    if (idx >= BL_ * (ED_/4)) return;
    int m  = idx >> 9;            // ED_/4 = 512
    int e4 = idx & 511;
    int e  = e4 * 4;
    int l  = m & (L_ - 1);

    float4 cur  = *(const float4*)(g_xs + (size_t)m * ED_ + e);
    float4 prev = (l > 0)      ? *(const float4*)(g_xs + (size_t)(m-1) * ED_ + e)
                               : make_float4(0.f,0.f,0.f,0.f);
    float4 nxt  = (l < L_-1)   ? *(const float4*)(g_xs + (size_t)(m+1) * ED_ + e)
                               : make_float4(0.f,0.f,0.f,0.f);

    // weights for 4 consecutive channels: 12 consecutive floats
    float4 w0 = *(const float4*)(w + (size_t)e*3);
    float4 w1 = *(const float4*)(w + (size_t)e*3 + 4);
    float4 w2 = *(const float4*)(w + (size_t)e*3 + 8);
    float4 bb = *(const float4*)(b + e);

    float r0 = fmaf(prev.x, w0.x, fmaf(cur.x, w0.y, fmaf(nxt.x, w0.z, bb.x)));
    float r1 = fmaf(prev.y, w0.w, fmaf(cur.y, w1.x, fmaf(nxt.y, w1.y, bb.y)));
    float r2 = fmaf(prev.z, w1.z, fmaf(cur.z, w1.w, fmaf(nxt.z, w2.x, bb.z)));
    float r3 = fmaf(prev.w, w2.y, fmaf(cur.w, w2.z, fmaf(nxt.w, w2.w, bb.w)));

    float4 o;
    o.x = r0 * (1.f / (1.f + __expf(-r0)));
    o.y = r1 * (1.f / (1.f + __expf(-r1)));
    o.z = r2 * (1.f / (1.f + __expf(-r2)));
    o.w = r3 * (1.f / (1.f + __expf(-r3)));
    *(float4*)(g_xsc + (size_t)m * ED_ + e) = o;
}

// ---------------- delta = softplus(x_dbl[:, :32] @ dt_proj_w^T + b) ----------------
// block: 256 threads; handles 8 m's x 256 e's.
__global__ void delta_kernel(const float* __restrict__ W,     // (ED, 32)
                             const float* __restrict__ bias)  // (ED)
{
    int mg = blockIdx.x >> 3;                     // group of 8 m's
    int e  = ((blockIdx.x & 7) << 8) + threadIdx.x;

    __shared__ float sx[8][32];
    {
        int i  = threadIdx.x;                     // 256 = 8*32 exactly
        int mm = i >> 5, r = i & 31;
        sx[mm][r] = g_xdbl[(size_t)(mg*8 + mm) * 64 + r];
    }
    __syncthreads();

    float wr[32];
#pragma unroll
    for (int q = 0; q < 8; q++) {
        float4 v = *(const float4*)(W + (size_t)e * 32 + q*4);
        wr[q*4+0] = v.x; wr[q*4+1] = v.y; wr[q*4+2] = v.z; wr[q*4+3] = v.w;
    }
    float bv = bias[e];

#pragma unroll
    for (int mm = 0; mm < 8; mm++) {
        float acc = bv;
#pragma unroll
        for (int r = 0; r < 32; r++) acc = fmaf(sx[mm][r], wr[r], acc);
        float sp = (acc > 20.f) ? acc : log1pf(__expf(acc));
        g_delta[(size_t)(mg*8 + mm) * ED_ + e] = sp;
    }
}

// ---------------- fused SSM step ----------------
// per (m, e): h_new = exp(delta*A)*h + delta*xs*Bp ; y = <h_new, C> + D*xs
// then g_y = y * silu(z). Writes h_new to output buffer.
__global__ void ssm_kernel(const float* __restrict__ h,
                           const float* __restrict__ Dvec,
                           float* __restrict__ hout)
{
    int tid = threadIdx.x;
    int m   = blockIdx.x >> 3;
    int e   = ((blockIdx.x & 7) << 8) + tid;

    __shared__ float sB[N_], sC[N_];
    if (tid < N_)            sB[tid]       = g_xdbl[(size_t)m * 64 + 32 + tid];
    else if (tid < 2 * N_)   sC[tid - N_]  = g_xdbl[(size_t)m * 64 + 32 + tid];
    __syncthreads();

    size_t me = (size_t)m * ED_ + e;
    float delta = g_delta[me];
    float xs    = g_xsc[me];
    float z     = g_z[me];
    float dx    = delta * xs;

    const float4* h4 = (const float4*)(h + me * N_);
    float4*       o4 = (float4*)(hout + me * N_);
    const float4* a4 = (const float4*)(g_A + (size_t)e * N_);

    float y = 0.f;
#pragma unroll
    for (int q = 0; q < 4; q++) {
        float4 hv = h4[q];
        float4 av = a4[q];
        float4 o;
        o.x = fmaf(__expf(delta * av.x), hv.x, dx * sB[q*4+0]);
        o.y = fmaf(__expf(delta * av.y), hv.y, dx * sB[q*4+1]);
        o.z = fmaf(__expf(delta * av.z), hv.z, dx * sB[q*4+2]);
        o.w = fmaf(__expf(delta * av.w), hv.w, dx * sB[q*4+3]);
        o4[q] = o;
        y = fmaf(o.x, sC[q*4+0], y);
        y = fmaf(o.y, sC[q*4+1], y);
        y = fmaf(o.z, sC[q*4+2], y);
        y = fmaf(o.w, sC[q*4+3], y);
    }
    y = fmaf(Dvec[e], xs, y);
    float sz = z * (1.f / (1.f + __expf(-z)));
    g_y[me] = y * sz;
}

// ---------------- launch ----------------
extern "C" void kernel_launch(void* const* d_in, const int* in_sizes, int n_in,
                              void* d_out, int out_size)
{
    const float* x          = (const float*)d_in[0];   // (2,1024,1024)
    const float* h          = (const float*)d_in[1];   // (2,1024,2048,16)
    const float* in_proj_w  = (const float*)d_in[2];   // (4096,1024)
    const float* conv_w     = (const float*)d_in[3];   // (2048,1,3)
    const float* conv_b     = (const float*)d_in[4];   // (2048)
    const float* x_proj_w   = (const float*)d_in[5];   // (64,2048)
    const float* dt_proj_w  = (const float*)d_in[6];   // (2048,32)
    const float* dt_proj_b  = (const float*)d_in[7];   // (2048)
    const float* A_log      = (const float*)d_in[8];   // (2048,16)
    const float* Dvec       = (const float*)d_in[9];   // (2048)
    const float* out_proj_w = (const float*)d_in[10];  // (1024,2048)

    float* out  = (float*)d_out;                 // (2,1024,1024) -> first 2,097,152
    float* hout = out + (size_t)BL_ * D_;        // h_new after it

    float* p_xsc  = nullptr;
    float* p_xdbl = nullptr;
    float* p_y    = nullptr;
    cudaGetSymbolAddress((void**)&p_xsc,  g_xsc);
    cudaGetSymbolAddress((void**)&p_xdbl, g_xdbl);
    cudaGetSymbolAddress((void**)&p_y,    g_y);

    // 1. A = -exp(A_log)
    prep_A_kernel<<<(ED_*N_ + 255)/256, 256>>>(A_log);

    // 2. in_proj GEMM: (2048x1024) x (4096x1024)^T -> split xs / z
    gemm_nt<128,128,16,8,8,1><<<dim3(NPROJ/128, BL_/128), 256>>>(
        x, in_proj_w, nullptr, BL_, NPROJ, D_);

    // 3. depthwise conv + silu
    conv_silu_kernel<<<(BL_ * (ED_/4) + 255)/256, 256>>>(conv_w, conv_b);

    // 4. x_proj GEMM: (2048x2048) x (64x2048)^T -> x_dbl
    gemm_nt<64,64,16,4,4,0><<<dim3(64/64, BL_/64), 256>>>(
        p_xsc, x_proj_w, p_xdbl, BL_, 64, ED_);

    // 5. dt_proj + softplus -> delta
    delta_kernel<<<(BL_/8) * 8, 256>>>(dt_proj_w, dt_proj_b);

    // 6. fused SSM (writes h_new to output + y*silu(z) scratch)
    ssm_kernel<<<BL_ * 8, 256>>>(h, Dvec, hout);

    // 7. out_proj GEMM: (2048x2048) x (1024x2048)^T -> out
    gemm_nt<128,128,16,8,8,0><<<dim3(D_/128, BL_/128), 256>>>(
        p_y, out_proj_w, out, BL_, D_, ED_);
}

// round 3
// speedup vs baseline: 1.6735x; 1.6735x over previous
#include <cuda_runtime.h>
#include <cstdint>

// Problem constants (fixed shapes)
#define BL_   2048           // B*L = 2*1024
#define L_    1024
#define D_    1024
#define ED_   2048
#define N_    16
#define R_    32
#define NPROJ 4096           // 2*ED

// ---------------- device scratch (static, no allocation) ----------------
__device__ float g_xs  [BL_ * ED_];
__device__ float g_z   [BL_ * ED_];
__device__ float g_xsc [BL_ * ED_];
__device__ float g_xdbl[BL_ * 64];
__device__ float g_xdbl_part[8][BL_ * 64];
__device__ float g_delta[BL_ * ED_];
__device__ float g_y   [BL_ * ED_];
__device__ float g_A   [ED_ * N_];

// ---------------- helpers ----------------
__device__ __forceinline__ uint32_t smem_u32(const void* p) {
    uint32_t a;
    asm("{ .reg .u64 t; cvta.to.shared.u64 t, %1; cvt.u32.u64 %0, t; }" : "=r"(a) : "l"(p));
    return a;
}
__device__ __forceinline__ uint32_t tf32_hi_bits(float a) {
    uint32_t b;
    asm("cvt.rna.tf32.f32 %0, %1;" : "=r"(b) : "f"(a));
    return b;
}

#define CP16(dst, src) \
    asm volatile("cp.async.cg.shared.global [%0], [%1], 16;" :: "r"(dst), "l"(src))
#define CP_COMMIT() asm volatile("cp.async.commit_group;")
template<int N> __device__ __forceinline__ void cp_wait() {
    asm volatile("cp.async.wait_group %0;" :: "n"(N));
}

#define MMA_TF32(c, a0, a1, a2, a3, b0, b1) \
    asm volatile("mma.sync.aligned.m16n8k8.row.col.f32.tf32.tf32.f32 " \
        "{%0,%1,%2,%3}, {%4,%5,%6,%7}, {%8,%9}, {%0,%1,%2,%3};" \
        : "+f"((c)[0]), "+f"((c)[1]), "+f"((c)[2]), "+f"((c)[3]) \
        : "r"(a0), "r"(a1), "r"(a2), "r"(a3), "r"(b0), "r"(b1))

// ============================================================
// 3xTF32 mma.sync GEMM: C[m][n] = sum_k A[m][k] * B[n][k]
// CTA 128x128, BK=32, 8 warps (2m x 4n), warp tile 64x32.
// SMEM: fp32 tiles, rows padded to 36 floats. cp.async double buffer.
// EPI 0: C[m*Nout + n]
// EPI 1: n0<2048 -> g_xs ; else -> g_z (col n-2048)
// ============================================================
#define SROW 36                      // padded row, floats
#define ATILE_F (128 * SROW)         // 4608 floats
#define STAGE_F (2 * ATILE_F)        // A + B per stage = 9216 floats
#define STAGE_B (STAGE_F * 4)        // 36864 bytes

template<int EPI>
__global__ void __launch_bounds__(256)
gemm_mma(const float* __restrict__ A, const float* __restrict__ B,
         float* __restrict__ C, int Nout, int K)
{
    extern __shared__ float sm[];
    const int tid  = threadIdx.x;
    const int wid  = tid >> 5;
    const int lane = tid & 31;
    const int gq   = lane >> 2;          // groupID 0..7
    const int tig  = lane & 3;           // thread-in-group 0..3
    const int m0   = blockIdx.y * 128;
    const int n0   = blockIdx.x * 128;
    const int wm   = (wid >> 2) * 64;    // warp m offset
    const int wn   = (wid & 3) * 32;     // warp n offset
    const int NC   = K >> 5;

    float acc[4][4][4];
#pragma unroll
    for (int i = 0; i < 4; i++)
#pragma unroll
        for (int j = 0; j < 4; j++)
#pragma unroll
            for (int q = 0; q < 4; q++) acc[i][j][q] = 0.f;

    const uint32_t sbase = smem_u32(sm);
    const int lr  = tid >> 3;            // 0..31 loader row
    const int lc4 = (tid & 7) << 2;      // loader col (floats)
    const float* ga = A + (size_t)(m0 + lr) * K + lc4;
    const float* gb = B + (size_t)(n0 + lr) * K + lc4;
    const uint32_t sa_off = (uint32_t)(lr * SROW + lc4) * 4;

    // ---- prologue: issue chunks 0 and 1 ----
#pragma unroll
    for (int c = 0; c < 2; c++) {
        uint32_t sa = sbase + c * STAGE_B + sa_off;
        uint32_t sbb = sa + ATILE_F * 4;
        const float* pa = ga + c * 32;
        const float* pb = gb + c * 32;
#pragma unroll
        for (int i = 0; i < 4; i++) {
            CP16(sa  + i * 32 * SROW * 4, pa + (size_t)(i * 32) * K);
            CP16(sbb + i * 32 * SROW * 4, pb + (size_t)(i * 32) * K);
        }
        CP_COMMIT();
    }
    cp_wait<1>();
    __syncthreads();

    for (int c = 0; c < NC; c++) {
        const int buf = c & 1;
        const float* As = sm + buf * STAGE_F;
        const float* Bs = As + ATILE_F;

#pragma unroll
        for (int ks = 0; ks < 4; ks++) {
            // B fragments for 4 n-tiles (hi/lo)
            uint32_t bhi[4][2], blo[4][2];
#pragma unroll
            for (int nt = 0; nt < 4; nt++) {
                const float* bp = Bs + (wn + 8 * nt + gq) * SROW + ks * 8 + tig;
                float b0 = bp[0], b1 = bp[4];
                bhi[nt][0] = tf32_hi_bits(b0);
                bhi[nt][1] = tf32_hi_bits(b1);
                blo[nt][0] = __float_as_uint(b0 - __uint_as_float(bhi[nt][0]));
                blo[nt][1] = __float_as_uint(b1 - __uint_as_float(bhi[nt][1]));
            }
#pragma unroll
            for (int mt = 0; mt < 4; mt++) {
                const float* ap = As + (wm + 16 * mt + gq) * SROW + ks * 8 + tig;
                float a0 = ap[0], a1 = ap[8 * SROW], a2 = ap[4], a3 = ap[8 * SROW + 4];
                uint32_t ah0 = tf32_hi_bits(a0), ah1 = tf32_hi_bits(a1);
                uint32_t ah2 = tf32_hi_bits(a2), ah3 = tf32_hi_bits(a3);
                uint32_t al0 = __float_as_uint(a0 - __uint_as_float(ah0));
                uint32_t al1 = __float_as_uint(a1 - __uint_as_float(ah1));
                uint32_t al2 = __float_as_uint(a2 - __uint_as_float(ah2));
                uint32_t al3 = __float_as_uint(a3 - __uint_as_float(ah3));
#pragma unroll
                for (int nt = 0; nt < 4; nt++) {
                    MMA_TF32(acc[mt][nt], ah0, ah1, ah2, ah3, bhi[nt][0], bhi[nt][1]);
                    MMA_TF32(acc[mt][nt], ah0, ah1, ah2, ah3, blo[nt][0], blo[nt][1]);
                    MMA_TF32(acc[mt][nt], al0, al1, al2, al3, bhi[nt][0], bhi[nt][1]);
                }
            }
        }
        __syncthreads();   // all warps done reading buf

        if (c + 2 < NC) {
            uint32_t sa = sbase + buf * STAGE_B + sa_off;
            uint32_t sbb = sa + ATILE_F * 4;
            const float* pa = ga + (c + 2) * 32;
            const float* pb = gb + (c + 2) * 32;
#pragma unroll
            for (int i = 0; i < 4; i++) {
                CP16(sa  + i * 32 * SROW * 4, pa + (size_t)(i * 32) * K);
                CP16(sbb + i * 32 * SROW * 4, pb + (size_t)(i * 32) * K);
            }
            CP_COMMIT();
            cp_wait<1>();
        } else {
            cp_wait<0>();
        }
        __syncthreads();
    }

    // ---- epilogue ----
    float* dst;
    int ld, ncol0;
    if (EPI == 1) {
        if (n0 < ED_) { dst = g_xs; ncol0 = n0; }
        else          { dst = g_z;  ncol0 = n0 - ED_; }
        ld = ED_;
    } else {
        dst = C; ncol0 = n0; ld = Nout;
    }
#pragma unroll
    for (int mt = 0; mt < 4; mt++) {
        const int m = m0 + wm + 16 * mt + gq;
#pragma unroll
        for (int nt = 0; nt < 4; nt++) {
            const int n = ncol0 + wn + 8 * nt + 2 * tig;
            float2 v0 = make_float2(acc[mt][nt][0], acc[mt][nt][1]);
            float2 v1 = make_float2(acc[mt][nt][2], acc[mt][nt][3]);
            *(float2*)(dst + (size_t)m * ld + n)       = v0;
            *(float2*)(dst + (size_t)(m + 8) * ld + n) = v1;
        }
    }
}

// ---------------- tiny precompute: A = -exp(A_log) ----------------
__global__ void prep_A_kernel(const float* __restrict__ A_log) {
    int i = blockIdx.x * blockDim.x + threadIdx.x;
    if (i < ED_ * N_) g_A[i] = -expf(A_log[i]);
}

// ---------------- split-K SIMT GEMM for x_proj ----------------
__global__ void __launch_bounds__(256)
gemm_xproj_sk(const float* __restrict__ A, const float* __restrict__ B, int K)
{
    constexpr int BM = 64, BN = 64, BK = 16, TM = 4, TN = 4;
    __shared__ float As[BK * BM];
    __shared__ float Bs[BK * BN];

    const int t  = threadIdx.x;
    const int m0 = blockIdx.y * BM;
    const int z  = blockIdx.z;
    const int KS = K >> 3;
    const int kbeg = z * KS;
    const int tr = t / (BN / TN);
    const int tc = t % (BN / TN);

    float acc[TM][TN];
#pragma unroll
    for (int i = 0; i < TM; i++)
#pragma unroll
        for (int j = 0; j < TN; j++) acc[i][j] = 0.f;

    for (int k0 = kbeg; k0 < kbeg + KS; k0 += BK) {
        {
            int row = t / (BK / 4);
            int cc  = t % (BK / 4);
            float4 v = *(const float4*)(A + (size_t)(m0 + row) * K + k0 + cc * 4);
            As[(cc * 4 + 0) * BM + row] = v.x;
            As[(cc * 4 + 1) * BM + row] = v.y;
            As[(cc * 4 + 2) * BM + row] = v.z;
            As[(cc * 4 + 3) * BM + row] = v.w;
            float4 w = *(const float4*)(B + (size_t)row * K + k0 + cc * 4);
            Bs[(cc * 4 + 0) * BN + row] = w.x;
            Bs[(cc * 4 + 1) * BN + row] = w.y;
            Bs[(cc * 4 + 2) * BN + row] = w.z;
            Bs[(cc * 4 + 3) * BN + row] = w.w;
        }
        __syncthreads();
#pragma unroll
        for (int kk = 0; kk < BK; kk++) {
            float af[TM], bf[TN];
#pragma unroll
            for (int i = 0; i < TM; i++) af[i] = As[kk * BM + tr * TM + i];
#pragma unroll
            for (int j = 0; j < TN; j++) bf[j] = Bs[kk * BN + tc * TN + j];
#pragma unroll
            for (int i = 0; i < TM; i++)
#pragma unroll
                for (int j = 0; j < TN; j++)
                    acc[i][j] = fmaf(af[i], bf[j], acc[i][j]);
        }
        __syncthreads();
    }
#pragma unroll
    for (int i = 0; i < TM; i++) {
        int m = m0 + tr * TM + i;
#pragma unroll
        for (int j = 0; j < TN; j++) {
            int n = tc * TN + j;
            g_xdbl_part[z][(size_t)m * 64 + n] = acc[i][j];
        }
    }
}

__global__ void reduce_xdbl_kernel() {
    int i = blockIdx.x * blockDim.x + threadIdx.x;
    if (i >= BL_ * 64 / 4) return;
    float4 s = make_float4(0.f, 0.f, 0.f, 0.f);
#pragma unroll
    for (int z = 0; z < 8; z++) {
        float4 v = *((const float4*)g_xdbl_part[z] + i);
        s.x += v.x; s.y += v.y; s.z += v.z; s.w += v.w;
    }
    *((float4*)g_xdbl + i) = s;
}

// ---------------- depthwise conv1d (k=3, pad 1) + silu ----------------
__global__ void conv_silu_kernel(const float* __restrict__ w,
                                 const float* __restrict__ b)
{
    int idx = blockIdx.x * blockDim.x + threadIdx.x;
    if (idx >= BL_ * (ED_ / 4)) return;
    int m  = idx >> 9;
    int e4 = idx & 511;
    int e  = e4 * 4;
    int l  = m & (L_ - 1);

    float4 cur  = *(const float4*)(g_xs + (size_t)m * ED_ + e);
    float4 prev = (l > 0)    ? *(const float4*)(g_xs + (size_t)(m - 1) * ED_ + e)
                             : make_float4(0.f, 0.f, 0.f, 0.f);
    float4 nxt  = (l < L_-1) ? *(const float4*)(g_xs + (size_t)(m + 1) * ED_ + e)
                             : make_float4(0.f, 0.f, 0.f, 0.f);

    float4 w0 = *(const float4*)(w + (size_t)e * 3);
    float4 w1 = *(const float4*)(w + (size_t)e * 3 + 4);
    float4 w2 = *(const float4*)(w + (size_t)e * 3 + 8);
    float4 bb = *(const float4*)(b + e);

    float r0 = fmaf(prev.x, w0.x, fmaf(cur.x, w0.y, fmaf(nxt.x, w0.z, bb.x)));
    float r1 = fmaf(prev.y, w0.w, fmaf(cur.y, w1.x, fmaf(nxt.y, w1.y, bb.y)));
    float r2 = fmaf(prev.z, w1.z, fmaf(cur.z, w1.w, fmaf(nxt.z, w2.x, bb.z)));
    float r3 = fmaf(prev.w, w2.y, fmaf(cur.w, w2.z, fmaf(nxt.w, w2.w, bb.w)));

    float4 o;
    o.x = r0 * (1.f / (1.f + __expf(-r0)));
    o.y = r1 * (1.f / (1.f + __expf(-r1)));
    o.z = r2 * (1.f / (1.f + __expf(-r2)));
    o.w = r3 * (1.f / (1.f + __expf(-r3)));
    *(float4*)(g_xsc + (size_t)m * ED_ + e) = o;
}

// ---------------- delta = softplus(x_dbl[:, :32] @ dt_proj_w^T + b) ----------------
__global__ void delta_kernel(const float* __restrict__ W,
                             const float* __restrict__ bias)
{
    int mg = blockIdx.x >> 3;
    int e  = ((blockIdx.x & 7) << 8) + threadIdx.x;

    __shared__ float sx[8][32];
    {
        int i  = threadIdx.x;
        int mm = i >> 5, r = i & 31;
        sx[mm][r] = g_xdbl[(size_t)(mg * 8 + mm) * 64 + r];
    }
    __syncthreads();

    float wr[32];
#pragma unroll
    for (int q = 0; q < 8; q++) {
        float4 v = *(const float4*)(W + (size_t)e * 32 + q * 4);
        wr[q * 4 + 0] = v.x; wr[q * 4 + 1] = v.y; wr[q * 4 + 2] = v.z; wr[q * 4 + 3] = v.w;
    }
    float bv = bias[e];

#pragma unroll
    for (int mm = 0; mm < 8; mm++) {
        float acc = bv;
#pragma unroll
        for (int r = 0; r < 32; r++) acc = fmaf(sx[mm][r], wr[r], acc);
        float sp = (acc > 20.f) ? acc : log1pf(__expf(acc));
        g_delta[(size_t)(mg * 8 + mm) * ED_ + e] = sp;
    }
}

// ---------------- fused SSM step ----------------
__global__ void ssm_kernel(const float* __restrict__ h,
                           const float* __restrict__ Dvec,
                           float* __restrict__ hout)
{
    int tid = threadIdx.x;
    int m   = blockIdx.x >> 3;
    int e   = ((blockIdx.x & 7) << 8) + tid;

    __shared__ float sB[N_], sC[N_];
    if (tid < N_)          sB[tid]      = g_xdbl[(size_t)m * 64 + 32 + tid];
    else if (tid < 2*N_)   sC[tid - N_] = g_xdbl[(size_t)m * 64 + 32 + tid];
    __syncthreads();

    size_t me = (size_t)m * ED_ + e;
    float delta = g_delta[me];
    float xs    = g_xsc[me];
    float z     = g_z[me];
    float dx    = delta * xs;

    const float4* h4 = (const float4*)(h + me * N_);
    float4*       o4 = (float4*)(hout + me * N_);
    const float4* a4 = (const float4*)(g_A + (size_t)e * N_);

    float y = 0.f;
#pragma unroll
    for (int q = 0; q < 4; q++) {
        float4 hv = h4[q];
        float4 av = a4[q];
        float4 o;
        o.x = fmaf(__expf(delta * av.x), hv.x, dx * sB[q*4+0]);
        o.y = fmaf(__expf(delta * av.y), hv.y, dx * sB[q*4+1]);
        o.z = fmaf(__expf(delta * av.z), hv.z, dx * sB[q*4+2]);
        o.w = fmaf(__expf(delta * av.w), hv.w, dx * sB[q*4+3]);
        o4[q] = o;
        y = fmaf(o.x, sC[q*4+0], y);
        y = fmaf(o.y, sC[q*4+1], y);
        y = fmaf(o.z, sC[q*4+2], y);
        y = fmaf(o.w, sC[q*4+3], y);
    }
    y = fmaf(Dvec[e], xs, y);
    float sz = z * (1.f / (1.f + __expf(-z)));
    g_y[me] = y * sz;
}

// ---------------- launch ----------------
extern "C" void kernel_launch(void* const* d_in, const int* in_sizes, int n_in,
                              void* d_out, int out_size)
{
    const float* x          = (const float*)d_in[0];
    const float* h          = (const float*)d_in[1];
    const float* in_proj_w  = (const float*)d_in[2];
    const float* conv_w     = (const float*)d_in[3];
    const float* conv_b     = (const float*)d_in[4];
    const float* x_proj_w   = (const float*)d_in[5];
    const float* dt_proj_w  = (const float*)d_in[6];
    const float* dt_proj_b  = (const float*)d_in[7];
    const float* A_log      = (const float*)d_in[8];
    const float* Dvec       = (const float*)d_in[9];
    const float* out_proj_w = (const float*)d_in[10];

    float* out  = (float*)d_out;
    float* hout = out + (size_t)BL_ * D_;

    float* p_xsc = nullptr;
    float* p_y   = nullptr;
    cudaGetSymbolAddress((void**)&p_xsc, g_xsc);
    cudaGetSymbolAddress((void**)&p_y,   g_y);

    const int SMEM_GEMM = 2 * STAGE_B;   // 73728 bytes
    cudaFuncSetAttribute(gemm_mma<0>, cudaFuncAttributeMaxDynamicSharedMemorySize, SMEM_GEMM);
    cudaFuncSetAttribute(gemm_mma<1>, cudaFuncAttributeMaxDynamicSharedMemorySize, SMEM_GEMM);

    // 1. A = -exp(A_log)
    prep_A_kernel<<<(ED_ * N_ + 255) / 256, 256>>>(A_log);

    // 2. in_proj GEMM (3xTF32 mma.sync): (2048x1024) x (4096x1024)^T -> split xs / z
    gemm_mma<1><<<dim3(NPROJ / 128, BL_ / 128), 256, SMEM_GEMM>>>(
        x, in_proj_w, nullptr, NPROJ, D_);

    // 3. depthwise conv + silu
    conv_silu_kernel<<<(BL_ * (ED_ / 4) + 255) / 256, 256>>>(conv_w, conv_b);

    // 4. x_proj GEMM (split-K SIMT) + reduce
    gemm_xproj_sk<<<dim3(1, BL_ / 64, 8), 256>>>(p_xsc, x_proj_w, ED_);
    reduce_xdbl_kernel<<<(BL_ * 64 / 4 + 255) / 256, 256>>>();

    // 5. dt_proj + softplus -> delta
    delta_kernel<<<(BL_ / 8) * 8, 256>>>(dt_proj_w, dt_proj_b);

    // 6. fused SSM (writes h_new to output + y*silu(z) scratch)
    ssm_kernel<<<BL_ * 8, 256>>>(h, Dvec, hout);

    // 7. out_proj GEMM (3xTF32 mma.sync): (2048x2048) x (1024x2048)^T -> out
    gemm_mma<0><<<dim3(D_ / 128, BL_ / 128), 256, SMEM_GEMM>>>(
        p_y, out_proj_w, out, D_, ED_);
}